// round 4
// baseline (speedup 1.0000x reference)
#include <cuda_runtime.h>
#include <cuda_bf16.h>
#include <cstdint>

#define BATCH 64
#define NNODE 50
#define FDIM 64
#define HDIM 128
#define EDGES 2450
#define TSTEPS 40
#define PS 136              // padded bf16 row stride (272B, 16B-aligned)
#define CHUNK 128
#define EPC 1225
#define MAXROWS 1536
#define NLOC 25
#define WSLOT (HDIM*PS*2)   // 34816 B per weight slot

// ---- smem byte offsets ----
#define OFF_W    0           // 4 slots = 139264
#define OFF_PRE  139264      // 34816 (pre tile, reused as m tile, then W3)
#define OFF_Y    174080      // 6400
#define OFF_B1   180480      // 1024
#define OFF_B2   181504      // 1024
#define OFF_B3   182528      // 256
#define OFF_AGG  182784      // 12800
#define OFF_RT   195584      // 512
#define SMEM_TOTAL 196096

// ---------------- device scratch ----------------
__device__ float          g_y[BATCH*NNODE*FDIM];
__device__ float          g_ksum[BATCH*NNODE*FDIM];
__device__ __nv_bfloat16  g_ybf[BATCH*NNODE*FDIM];
__device__ __nv_bfloat16  g_Wt[4*HDIM*PS];   // [slot][n][k]
__device__ int            g_rows[128*MAXROWS];
__device__ int            g_nrows[128];

// ---------------- helpers ----------------
__device__ __forceinline__ void mma16816(float* c, const uint32_t* a, const uint32_t* b) {
    asm volatile(
        "mma.sync.aligned.m16n8k16.row.col.f32.bf16.bf16.f32 "
        "{%0,%1,%2,%3}, {%4,%5,%6,%7}, {%8,%9}, {%0,%1,%2,%3};\n"
        : "+f"(c[0]), "+f"(c[1]), "+f"(c[2]), "+f"(c[3])
        : "r"(a[0]), "r"(a[1]), "r"(a[2]), "r"(a[3]), "r"(b[0]), "r"(b[1]));
}
__device__ __forceinline__ void ldsm4(uint32_t& r0, uint32_t& r1, uint32_t& r2, uint32_t& r3,
                                      uint32_t addr) {
    asm volatile("ldmatrix.sync.aligned.m8n8.x4.shared.b16 {%0,%1,%2,%3}, [%4];"
                 : "=r"(r0), "=r"(r1), "=r"(r2), "=r"(r3) : "r"(addr));
}
__device__ __forceinline__ uint32_t smem_u32(const void* p) {
    uint32_t a;
    asm("{ .reg .u64 t; cvta.to.shared.u64 t, %1; cvt.u32.u64 %0, t; }" : "=r"(a) : "l"(p));
    return a;
}
__device__ __forceinline__ uint32_t packbf(float x, float y) {
    __nv_bfloat162 t = __floats2bfloat162_rn(x, y);
    return *reinterpret_cast<uint32_t*>(&t);
}

// ---------------- prep ----------------
__global__ void prep_kernel(const float* __restrict__ fp,
                            const float* __restrict__ W1,
                            const float* __restrict__ W2,
                            float* __restrict__ out) {
    int gsz = gridDim.x * blockDim.x;
    int g0  = blockIdx.x * blockDim.x + threadIdx.x;
    for (int i = g0; i < 4*HDIM*HDIM; i += gsz) {
        int s = i >> 14, rem = i & 16383;
        int n = rem >> 7, k = rem & 127;
        float v = (s < 2) ? W1[s*16384 + k*HDIM + n] : W2[(s-2)*16384 + k*HDIM + n];
        g_Wt[s*(HDIM*PS) + n*PS + k] = __float2bfloat16(v);
    }
    for (int i = g0; i < BATCH*NNODE*FDIM; i += gsz) {
        float v = fp[i];
        g_y[i]   = v;
        g_ybf[i] = __float2bfloat16(v);
        out[(i >> 6)*(TSTEPS*FDIM) + (i & 63)] = v;
    }
}

// ---------------- sort: stable partition by type (receiver order kept) ----------------
__global__ void sort_kernel(const int* __restrict__ graph) {
    const int cta  = blockIdx.x;
    const int b    = cta >> 1;
    const int base = (cta & 1) * EPC;
    const int lane = threadIdx.x;
    int* rows = g_rows + cta * MAXROWS;
    int row = 0;
#pragma unroll
    for (int k = 0; k < 2; ++k) {
        for (int i0 = 0; i0 < EPC; i0 += 32) {
            int i = i0 + lane;
            bool m = false; int meta = 0;
            if (i < EPC) {
                int e = base + i;
                int kk = graph[b*EDGES + e];
                int r = e / 49, j = e - r*49;
                int s = j + (j >= r);
                meta = (kk << 16) | (r << 8) | s;
                m = (kk == k);
            }
            unsigned mask = __ballot_sync(0xffffffffu, m);
            if (m) rows[row + __popc(mask & ((1u << lane) - 1u))] = meta;
            row += __popc(mask);
        }
        int pad = (128 - (row & 127)) & 127;
        for (int i = lane; i < pad; i += 32) rows[row + i] = -1;
        row += pad;
    }
    if (lane == 0) g_nrows[cta] = row;
}

// ---------------- fused edge+node kernel ----------------
__global__ void __launch_bounds__(256, 1)
edge_kernel(const float* __restrict__ b1f, const float* __restrict__ b2f,
            const float* __restrict__ W3,  const float* __restrict__ b3f,
            const float* __restrict__ ts,  int t, int stage,
            float* __restrict__ out) {
    extern __shared__ char smb[];
    const int tid  = threadIdx.x;
    const int lane = tid & 31, wid = tid >> 5;
    const int cta  = blockIdx.x;
    const int b = cta >> 1, hb = cta & 1;

    // load weights, y[b], biases; zero agg
    {
        const uint4* src = reinterpret_cast<const uint4*>(g_Wt);
        uint4* dst = reinterpret_cast<uint4*>(smb + OFF_W);
        for (int i = tid; i < 139264/16; i += 256) dst[i] = src[i];
    }
    {
        const uint4* src = reinterpret_cast<const uint4*>(g_ybf + b*NNODE*FDIM);
        uint4* dst = reinterpret_cast<uint4*>(smb + OFF_Y);
        for (int i = tid; i < 6400/16; i += 256) dst[i] = src[i];
    }
    ((float*)(smb + OFF_B1))[tid] = b1f[tid];
    ((float*)(smb + OFF_B2))[tid] = b2f[tid];
    if (tid < 64) ((float*)(smb + OFF_B3))[tid] = b3f[tid];
    {
        float* agg = (float*)(smb + OFF_AGG);
        for (int i = tid; i < NLOC*HDIM; i += 256) agg[i] = 0.f;
    }
    __syncthreads();

    const float* sB1 = (float*)(smb + OFF_B1);
    const float* sB2 = (float*)(smb + OFF_B2);
    int* sRt = (int*)(smb + OFF_RT);
    __nv_bfloat16* sPre = (__nv_bfloat16*)(smb + OFF_PRE);

    const int nch = g_nrows[cta] >> 7;
    const int* __restrict__ rows = g_rows + cta * MAXROWS;

    // warp owns rows rm..rm+15 of every tile
    const int rm  = wid * 16;
    const int g   = lane >> 2, tig = lane & 3;

    // ldmatrix per-lane addresses
    const int li = lane & 7, lm = lane >> 3;
    // A (pre tile): matrix m: rows rm + (m&1)*8 + i, col half (m>>1)*8
    const uint32_t aAddr = smem_u32(sPre) +
        (uint32_t)(((rm + (lm & 1)*8 + li)*PS + (lm >> 1)*8) * 2);
    // B (weight tile): matrix m: n-row = (m>>1)*8 + i, col half (m&1)*8
    const uint32_t sWaddr = smem_u32(smb + OFF_W);
    const uint32_t bLane = (uint32_t)((((lm >> 1)*8 + li)*PS + (lm & 1)*8) * 2);

    for (int ch = 0; ch < nch; ++ch) {
        const int* crow = rows + ch*CHUNK;
        const int k = (crow[0] >> 16);            // chunk is single-type

        // per-warp: build own 16 pre rows + receiver meta
        {
            int row = rm + (lane >> 1), hlf = lane & 1;
            int v = crow[rm + (lane >> 1)];
            if (hlf == 0) sRt[row] = (v < 0) ? -1 : ((v >> 8) & 255);
            uint4* dst = reinterpret_cast<uint4*>(sPre + row*PS + hlf*64);
            if (v >= 0) {
                int node = hlf ? ((v >> 8) & 255) : (v & 255);
                const uint4* src = (const uint4*)(smb + OFF_Y + node*FDIM*2);
#pragma unroll
                for (int q = 0; q < 8; ++q) dst[q] = src[q];
            } else {
                uint4 z = make_uint4(0,0,0,0);
#pragma unroll
                for (int q = 0; q < 8; ++q) dst[q] = z;
            }
        }
        __syncwarp();

        const uint32_t bAddr1 = sWaddr + (uint32_t)(k*WSLOT) + bLane;
        const uint32_t bAddr2 = sWaddr + (uint32_t)((2 + k)*WSLOT) + bLane;

        // ---- GEMM1: C1[16 rows x 128 cols] = pre @ W1[k]^T ----
        float C[16][4];
#pragma unroll
        for (int i = 0; i < 16; ++i) { C[i][0]=0.f; C[i][1]=0.f; C[i][2]=0.f; C[i][3]=0.f; }
#pragma unroll
        for (int kb = 0; kb < 8; ++kb) {
            uint32_t a[4];
            ldsm4(a[0], a[1], a[2], a[3], aAddr + kb*32);
#pragma unroll
            for (int p = 0; p < 8; ++p) {
                uint32_t bfr[4];
                ldsm4(bfr[0], bfr[1], bfr[2], bfr[3],
                      bAddr1 + (uint32_t)(p*(16*PS*2) + kb*32));
                mma16816(C[2*p],     a, bfr);
                mma16816(C[2*p + 1], a, bfr + 2);
            }
        }

        // epilogue1 (in registers): h = relu(C1 + b1[k]) -> A-frags of GEMM2
        uint32_t afr[8][4];
#pragma unroll
        for (int kt = 0; kt < 8; ++kt) {
            int c0 = (2*kt)*8 + 2*tig, c1 = c0 + 8;
            float b00 = sB1[k*HDIM + c0], b01 = sB1[k*HDIM + c0 + 1];
            float b10 = sB1[k*HDIM + c1], b11 = sB1[k*HDIM + c1 + 1];
            float* x = C[2*kt]; float* y2 = C[2*kt + 1];
            afr[kt][0] = packbf(fmaxf(x[0]+b00,0.f),  fmaxf(x[1]+b01,0.f));
            afr[kt][1] = packbf(fmaxf(x[2]+b00,0.f),  fmaxf(x[3]+b01,0.f));
            afr[kt][2] = packbf(fmaxf(y2[0]+b10,0.f), fmaxf(y2[1]+b11,0.f));
            afr[kt][3] = packbf(fmaxf(y2[2]+b10,0.f), fmaxf(y2[3]+b11,0.f));
        }

        // ---- GEMM2: C2 = h @ W2[k]^T (A straight from registers) ----
#pragma unroll
        for (int i = 0; i < 16; ++i) { C[i][0]=0.f; C[i][1]=0.f; C[i][2]=0.f; C[i][3]=0.f; }
#pragma unroll
        for (int kb = 0; kb < 8; ++kb) {
#pragma unroll
            for (int p = 0; p < 8; ++p) {
                uint32_t bfr[4];
                ldsm4(bfr[0], bfr[1], bfr[2], bfr[3],
                      bAddr2 + (uint32_t)(p*(16*PS*2) + kb*32));
                mma16816(C[2*p],     afr[kb], bfr);
                mma16816(C[2*p + 1], afr[kb], bfr + 2);
            }
        }

        // epilogue2: m = relu(C2 + b2[k]) -> own rows of pre tile (reuse as m)
#pragma unroll
        for (int nt = 0; nt < 16; ++nt) {
            int c0 = nt*8 + 2*tig;
            float b0v = sB2[k*HDIM + c0], b1v = sB2[k*HDIM + c0 + 1];
            float* x = C[nt];
            *reinterpret_cast<uint32_t*>(&sPre[(rm + g)*PS + c0]) =
                packbf(fmaxf(x[0]+b0v,0.f), fmaxf(x[1]+b1v,0.f));
            *reinterpret_cast<uint32_t*>(&sPre[(rm + g + 8)*PS + c0]) =
                packbf(fmaxf(x[2]+b0v,0.f), fmaxf(x[3]+b1v,0.f));
        }
        __syncthreads();

        // segmented aggregation (receiver-sorted rows) into smem agg
        {
            int col = tid & 127;
            int rb = (tid < 128) ? 0 : 64;
            int re = rb + 64;
            float* agg = (float*)(smb + OFF_AGG);
            const int rbase = hb * NLOC;
            float acc = 0.f; int cur = -1;
            for (int row = rb; row < re; ++row) {
                int rr = sRt[row];
                if (rr != cur) {
                    if (cur >= 0) atomicAdd(&agg[(cur - rbase)*HDIM + col], acc);
                    acc = 0.f; cur = rr;
                }
                if (rr < 0) continue;
                acc += __bfloat162float(sPre[row*PS + col]);
            }
            if (cur >= 0) atomicAdd(&agg[(cur - rbase)*HDIM + col], acc);
        }
        __syncthreads();
    }

    // ---- node phase: kv = tanh(agg/N @ W3 + b3); RK4 stage update ----
    {
        float* w3 = (float*)(smb + OFF_PRE);   // reuse pre area (32KB <= 34.8KB)
        for (int i = tid; i < HDIM*FDIM; i += 256) w3[i] = W3[i];
    }
    __syncthreads();
    {
        const float dt = ts[t+1] - ts[t];
        const float inv_n = 1.0f / (float)NNODE;
        const float* agg = (float*)(smb + OFF_AGG);
        const float* w3  = (float*)(smb + OFF_PRE);
        const float* sb3 = (float*)(smb + OFF_B3);
        for (int idx = tid; idx < NLOC*FDIM; idx += 256) {
            int n = idx >> 6, j = idx & 63;
            const float* ar = agg + n*HDIM;
            float acc = 0.f;
#pragma unroll 8
            for (int h = 0; h < HDIM; ++h)
                acc = fmaf(ar[h], w3[h*FDIM + j], acc);
            float kv = tanhf(acc * inv_n + sb3[j]);
            int gi = (b*NNODE + hb*NLOC + n)*FDIM + j;
            float yv = g_y[gi];
            float yin;
            if (stage == 0)      { g_ksum[gi] = kv;        yin = yv + 0.5f*dt*kv; }
            else if (stage == 1) { g_ksum[gi] += 2.f*kv;   yin = yv + 0.5f*dt*kv; }
            else if (stage == 2) { g_ksum[gi] += 2.f*kv;   yin = yv + dt*kv; }
            else {
                float yn = yv + dt*(1.f/6.f)*(g_ksum[gi] + kv);
                g_y[gi] = yn;
                out[(b*NNODE + hb*NLOC + n)*(TSTEPS*FDIM) + (t+1)*FDIM + j] = yn;
                yin = yn;
            }
            g_ybf[gi] = __float2bfloat16(yin);
        }
    }
}

// ---------------- launcher ----------------
extern "C" void kernel_launch(void* const* d_in, const int* in_sizes, int n_in,
                              void* d_out, int out_size) {
    const float* fp    = (const float*)d_in[0];
    const float* ts    = (const float*)d_in[1];
    const int*   graph = (const int*)d_in[2];
    const float* W1    = (const float*)d_in[3];
    const float* b1    = (const float*)d_in[4];
    const float* W2    = (const float*)d_in[5];
    const float* b2    = (const float*)d_in[6];
    const float* W3    = (const float*)d_in[7];
    const float* b3    = (const float*)d_in[8];
    float* out = (float*)d_out;

    cudaFuncSetAttribute(edge_kernel, cudaFuncAttributeMaxDynamicSharedMemorySize, SMEM_TOTAL);

    prep_kernel<<<256, 256>>>(fp, W1, W2, out);
    sort_kernel<<<128, 32>>>(graph);
    for (int t = 0; t < TSTEPS - 1; ++t)
        for (int st = 0; st < 4; ++st)
            edge_kernel<<<128, 256, SMEM_TOTAL>>>(b1, b2, W3, b3, ts, t, st, out);
}

// round 5
// speedup vs baseline: 1.1134x; 1.1134x over previous
#include <cuda_runtime.h>
#include <cuda_bf16.h>
#include <cstdint>

#define BATCH 64
#define NNODE 50
#define FDIM 64
#define HDIM 128
#define EDGES 2450
#define TSTEPS 40
#define CHUNK 128
#define MAXROWS 896
#define NQ 4                 // quarters per batch
#define NCTA (BATCH*NQ)      // 256

// ---- smem byte offsets ----
#define OFF_W    0           // 4 tiles x 16KB = 65536 (W1 h0,h1, W2 h0,h1 of current k)
#define OFF_PRE0 65536       // 16384 (send half / h half0 / m half0; later W3 part)
#define OFF_PRE1 81920       // 16384
#define OFF_Y    98304       // 6400
#define OFF_B1   104704      // 1024
#define OFF_B2   105728      // 1024
#define OFF_B3   106752      // 256
#define OFF_AGG  107008      // 13*128*4 = 6656
#define OFF_RT   113664      // 512
#define SMEM_TOTAL 114176

#define SWZ(o) ((o) ^ (((o) >> 3) & 0x70))

// ---------------- device scratch ----------------
__device__ float          g_y[BATCH*NNODE*FDIM];
__device__ float          g_ksum[BATCH*NNODE*FDIM];
__device__ __nv_bfloat16  g_ybf[BATCH*NNODE*FDIM];
__device__ __nv_bfloat16  g_Wt[8*8192];        // 8 swizzled 16KB tiles: slot*2+half
__device__ int            g_rows[NCTA*MAXROWS];
__device__ int            g_nrows[NCTA];

// ---------------- helpers ----------------
__device__ __forceinline__ void mma16816(float* c, const uint32_t* a, const uint32_t* b) {
    asm volatile(
        "mma.sync.aligned.m16n8k16.row.col.f32.bf16.bf16.f32 "
        "{%0,%1,%2,%3}, {%4,%5,%6,%7}, {%8,%9}, {%0,%1,%2,%3};\n"
        : "+f"(c[0]), "+f"(c[1]), "+f"(c[2]), "+f"(c[3])
        : "r"(a[0]), "r"(a[1]), "r"(a[2]), "r"(a[3]), "r"(b[0]), "r"(b[1]));
}
__device__ __forceinline__ void ldsm4(uint32_t* r, uint32_t addr) {
    asm volatile("ldmatrix.sync.aligned.m8n8.x4.shared.b16 {%0,%1,%2,%3}, [%4];"
                 : "=r"(r[0]), "=r"(r[1]), "=r"(r[2]), "=r"(r[3]) : "r"(addr));
}
__device__ __forceinline__ uint32_t smem_u32(const void* p) {
    uint32_t a;
    asm("{ .reg .u64 t; cvta.to.shared.u64 t, %1; cvt.u32.u64 %0, t; }" : "=r"(a) : "l"(p));
    return a;
}
__device__ __forceinline__ uint32_t packbf(float x, float y) {
    __nv_bfloat162 t = __floats2bfloat162_rn(x, y);
    return *reinterpret_cast<uint32_t*>(&t);
}

// ---------------- prep: weights -> swizzled bf16 tiles ----------------
__global__ void prep_kernel(const float* __restrict__ fp,
                            const float* __restrict__ W1,
                            const float* __restrict__ W2,
                            float* __restrict__ out) {
    int gsz = gridDim.x * blockDim.x;
    int g0  = blockIdx.x * blockDim.x + threadIdx.x;
    for (int i = g0; i < 4*HDIM*HDIM; i += gsz) {
        int s = i >> 14, rem = i & 16383;
        int n = rem >> 7, k = rem & 127;
        float v = (s < 2) ? W1[s*16384 + k*HDIM + n] : W2[(s-2)*16384 + k*HDIM + n];
        int tile = s*2 + (k >> 6);
        uint32_t boff = (uint32_t)(n*128 + (k & 63)*2);
        g_Wt[tile*8192 + (SWZ(boff) >> 1)] = __float2bfloat16(v);
    }
    for (int i = g0; i < BATCH*NNODE*FDIM; i += gsz) {
        float v = fp[i];
        g_y[i]   = v;
        g_ybf[i] = __float2bfloat16(v);
        out[(i >> 6)*(TSTEPS*FDIM) + (i & 63)] = v;
    }
}

// ---------------- sort: per-quarter stable partition by type ----------------
__global__ void sort_kernel(const int* __restrict__ graph) {
    const int cta = blockIdx.x;           // b*4 + q
    const int b = cta >> 2, q = cta & 3;
    const int rstart = (q < 2) ? q*13 : 26 + (q-2)*12;
    const int rcnt   = (q < 2) ? 13 : 12;
    const int ebase  = rstart * 49;
    const int ecnt   = rcnt * 49;
    const int lane = threadIdx.x;
    int* rows = g_rows + cta * MAXROWS;
    int row = 0;
#pragma unroll
    for (int k = 0; k < 2; ++k) {
        for (int i0 = 0; i0 < ecnt; i0 += 32) {
            int i = i0 + lane;
            bool m = false; int meta = 0;
            if (i < ecnt) {
                int e = ebase + i;
                int kk = graph[b*EDGES + e];
                int r = e / 49, j = e - r*49;
                int s = j + (j >= r);
                meta = (kk << 16) | (r << 8) | s;
                m = (kk == k);
            }
            unsigned mask = __ballot_sync(0xffffffffu, m);
            if (m) rows[row + __popc(mask & ((1u << lane) - 1u))] = meta;
            row += __popc(mask);
        }
        int pad = (128 - (row & 127)) & 127;
        for (int i = lane; i < pad; i += 32) rows[row + i] = -1;
        row += pad;
    }
    if (lane == 0) g_nrows[cta] = row;
}

// ---------------- fused edge+node kernel ----------------
__global__ void __launch_bounds__(256, 2)
edge_kernel(const float* __restrict__ b1f, const float* __restrict__ b2f,
            const float* __restrict__ W3,  const float* __restrict__ b3f,
            const float* __restrict__ ts,  int t, int stage,
            float* __restrict__ out) {
    extern __shared__ char smb[];
    const int tid  = threadIdx.x;
    const int lane = tid & 31, wid = tid >> 5;
    const int cta  = blockIdx.x;
    const int b = cta >> 2, q = cta & 3;
    const int rstart = (q < 2) ? q*13 : 26 + (q-2)*12;
    const int nloc   = (q < 2) ? 13 : 12;

    // load y[b], biases; zero agg
    {
        const uint4* src = reinterpret_cast<const uint4*>(g_ybf + b*NNODE*FDIM);
        uint4* dst = reinterpret_cast<uint4*>(smb + OFF_Y);
        for (int i = tid; i < 6400/16; i += 256) dst[i] = src[i];
    }
    ((float*)(smb + OFF_B1))[tid] = b1f[tid];
    ((float*)(smb + OFF_B2))[tid] = b2f[tid];
    if (tid < 64) ((float*)(smb + OFF_B3))[tid] = b3f[tid];
    {
        float* agg = (float*)(smb + OFF_AGG);
        for (int i = tid; i < nloc*HDIM; i += 256) agg[i] = 0.f;
    }

    const float* sB1 = (float*)(smb + OFF_B1);
    const float* sB2 = (float*)(smb + OFF_B2);
    int* sRt = (int*)(smb + OFF_RT);

    const int nch = g_nrows[cta] >> 7;
    const int* __restrict__ rows = g_rows + cta * MAXROWS;

    // warp tiling: wm in {0,64}, wn in {0,32,64,96}
    const int wm = (wid & 1) * 64;
    const int wn = (wid >> 1) * 32;
    const int g = lane >> 2, tig = lane & 3;
    const int li = lane & 7, lm = lane >> 3;
    // ldmatrix lane invariants
    const int aRow = (lm & 1)*8 + li;      // within 16-row block
    const int aK16 = (lm >> 1) * 16;       // byte offset within 32B k-group
    const int bRow = (lm >> 1)*8 + li;
    const int bK16 = (lm & 1) * 16;

    const uint32_t uPre0 = smem_u32(smb + OFF_PRE0);
    const uint32_t uPre1 = smem_u32(smb + OFF_PRE1);
    const uint32_t uW    = smem_u32(smb + OFF_W);

    int curk = -1;

    for (int ch = 0; ch < nch; ++ch) {
        const int* crow = rows + ch*CHUNK;
        const int k = (crow[0] >> 16);     // chunk single-type; first row valid

        // weight (re)load on type change: W1[k] tiles 2k,2k+1; W2[k] tiles 2(2+k)..
        if (k != curk) {
            curk = k;
            const uint4* s1 = reinterpret_cast<const uint4*>(g_Wt + (k*2)*8192);
            const uint4* s2 = reinterpret_cast<const uint4*>(g_Wt + ((2 + k)*2)*8192);
            uint4* d1 = reinterpret_cast<uint4*>(smb + OFF_W);
            uint4* d2 = reinterpret_cast<uint4*>(smb + OFF_W + 32768);
            for (int i = tid; i < 2048; i += 256) { d1[i] = s1[i]; d2[i] = s2[i]; }
        }

        // build pre tile halves + receiver meta (2 threads/row)
        {
            int row = tid >> 1, hlf = tid & 1;
            int v = crow[row];
            if (hlf == 0) sRt[row] = (v < 0) ? -1 : ((v >> 8) & 255);
            char* tb = smb + (hlf ? OFF_PRE1 : OFF_PRE0);
            if (v >= 0) {
                int node = hlf ? ((v >> 8) & 255) : (v & 255);
                const uint4* src = (const uint4*)(smb + OFF_Y + node*FDIM*2);
#pragma unroll
                for (int qq = 0; qq < 8; ++qq) {
                    uint32_t o = (uint32_t)(row*128 + qq*16);
                    *(uint4*)(tb + SWZ(o)) = src[qq];
                }
            } else {
                uint4 z = make_uint4(0,0,0,0);
#pragma unroll
                for (int qq = 0; qq < 8; ++qq) {
                    uint32_t o = (uint32_t)(row*128 + qq*16);
                    *(uint4*)(tb + SWZ(o)) = z;
                }
            }
        }
        __syncthreads();

        float C[16][4];

        // ==== GEMM1: C = pre @ W1[k]^T  (A: PRE halves, B: smem W tiles 0,1) ====
#pragma unroll
        for (int i = 0; i < 16; ++i) { C[i][0]=0.f; C[i][1]=0.f; C[i][2]=0.f; C[i][3]=0.f; }
#pragma unroll
        for (int kb = 0; kb < 8; ++kb) {
            const int half = kb >> 2;
            const uint32_t kgrp = (uint32_t)((kb & 3) * 32);
            const uint32_t aBase = half ? uPre1 : uPre0;
            uint32_t a[4][4];
#pragma unroll
            for (int mt = 0; mt < 4; ++mt) {
                uint32_t o = (uint32_t)((wm + mt*16 + aRow)*128) + kgrp + aK16;
                ldsm4(a[mt], aBase + SWZ(o));
            }
            uint32_t bf[2][4];
#pragma unroll
            for (int nt2 = 0; nt2 < 2; ++nt2) {
                uint32_t o = (uint32_t)((wn + nt2*16 + bRow)*128) + kgrp + bK16;
                ldsm4(bf[nt2], uW + half*16384u + SWZ(o));
            }
#pragma unroll
            for (int mt = 0; mt < 4; ++mt)
#pragma unroll
                for (int nt = 0; nt < 4; ++nt)
                    mma16816(C[mt*4 + nt], a[mt], &bf[nt >> 1][(nt & 1)*2]);
        }
        __syncthreads();   // all GEMM1 reads of PRE done

        // epilogue1: h = relu(C + b1[k]) -> PRE halves (swizzled bf16)
        {
            const int hh = wn >> 6;
            char* tb = smb + (hh ? OFF_PRE1 : OFF_PRE0);
#pragma unroll
            for (int mt = 0; mt < 4; ++mt)
#pragma unroll
                for (int nt = 0; nt < 4; ++nt) {
                    int r0 = wm + mt*16 + g, r1 = r0 + 8;
                    int c = wn + nt*8 + 2*tig;
                    float b0v = sB1[k*HDIM + c], b1v = sB1[k*HDIM + c + 1];
                    float* x = C[mt*4 + nt];
                    uint32_t cb = (uint32_t)((c & 63)*2);
                    *(uint32_t*)(tb + SWZ((uint32_t)(r0*128) + cb)) =
                        packbf(fmaxf(x[0]+b0v,0.f), fmaxf(x[1]+b1v,0.f));
                    *(uint32_t*)(tb + SWZ((uint32_t)(r1*128) + cb)) =
                        packbf(fmaxf(x[2]+b0v,0.f), fmaxf(x[3]+b1v,0.f));
                }
        }
        __syncthreads();

        // ==== GEMM2: C = h @ W2[k]^T (A: PRE halves = h, B: W tiles 2,3) ====
#pragma unroll
        for (int i = 0; i < 16; ++i) { C[i][0]=0.f; C[i][1]=0.f; C[i][2]=0.f; C[i][3]=0.f; }
#pragma unroll
        for (int kb = 0; kb < 8; ++kb) {
            const int half = kb >> 2;
            const uint32_t kgrp = (uint32_t)((kb & 3) * 32);
            const uint32_t aBase = half ? uPre1 : uPre0;
            uint32_t a[4][4];
#pragma unroll
            for (int mt = 0; mt < 4; ++mt) {
                uint32_t o = (uint32_t)((wm + mt*16 + aRow)*128) + kgrp + aK16;
                ldsm4(a[mt], aBase + SWZ(o));
            }
            uint32_t bf[2][4];
#pragma unroll
            for (int nt2 = 0; nt2 < 2; ++nt2) {
                uint32_t o = (uint32_t)((wn + nt2*16 + bRow)*128) + kgrp + bK16;
                ldsm4(bf[nt2], uW + 32768u + half*16384u + SWZ(o));
            }
#pragma unroll
            for (int mt = 0; mt < 4; ++mt)
#pragma unroll
                for (int nt = 0; nt < 4; ++nt)
                    mma16816(C[mt*4 + nt], a[mt], &bf[nt >> 1][(nt & 1)*2]);
        }
        __syncthreads();   // all GEMM2 reads done

        // epilogue2: m = relu(C + b2[k]) -> PRE halves
        {
            const int hh = wn >> 6;
            char* tb = smb + (hh ? OFF_PRE1 : OFF_PRE0);
#pragma unroll
            for (int mt = 0; mt < 4; ++mt)
#pragma unroll
                for (int nt = 0; nt < 4; ++nt) {
                    int r0 = wm + mt*16 + g, r1 = r0 + 8;
                    int c = wn + nt*8 + 2*tig;
                    float b0v = sB2[k*HDIM + c], b1v = sB2[k*HDIM + c + 1];
                    float* x = C[mt*4 + nt];
                    uint32_t cb = (uint32_t)((c & 63)*2);
                    *(uint32_t*)(tb + SWZ((uint32_t)(r0*128) + cb)) =
                        packbf(fmaxf(x[0]+b0v,0.f), fmaxf(x[1]+b1v,0.f));
                    *(uint32_t*)(tb + SWZ((uint32_t)(r1*128) + cb)) =
                        packbf(fmaxf(x[2]+b0v,0.f), fmaxf(x[3]+b1v,0.f));
                }
        }
        __syncthreads();

        // segmented aggregation (receiver-sorted rows) into smem agg
        {
            int col = tid & 127;
            int rb = (tid < 128) ? 0 : 64;
            int re = rb + 64;
            const int hh = col >> 6;
            const char* tb = smb + (hh ? OFF_PRE1 : OFF_PRE0);
            uint32_t cb = (uint32_t)((col & 63)*2);
            float* agg = (float*)(smb + OFF_AGG);
            float acc = 0.f; int cur = -1;
            for (int row = rb; row < re; ++row) {
                int rr = sRt[row];
                if (rr != cur) {
                    if (cur >= 0) atomicAdd(&agg[(cur - rstart)*HDIM + col], acc);
                    acc = 0.f; cur = rr;
                }
                if (rr < 0) continue;
                acc += __bfloat162float(*(const __nv_bfloat16*)(tb + SWZ((uint32_t)(row*128) + cb)));
            }
            if (cur >= 0) atomicAdd(&agg[(cur - rstart)*HDIM + col], acc);
        }
        __syncthreads();
    }

    // ---- node phase: kv = tanh(agg/N @ W3 + b3); RK4 stage update ----
    {
        float* w3 = (float*)(smb + OFF_PRE0);   // 32KB, exactly PRE0+PRE1
        for (int i = tid; i < HDIM*FDIM; i += 256) w3[i] = W3[i];
    }
    __syncthreads();
    {
        const float dt = ts[t+1] - ts[t];
        const float inv_n = 1.0f / (float)NNODE;
        const float* agg = (float*)(smb + OFF_AGG);
        const float* w3  = (float*)(smb + OFF_PRE0);
        const float* sb3 = (float*)(smb + OFF_B3);
        for (int idx = tid; idx < nloc*FDIM; idx += 256) {
            int n = idx >> 6, j = idx & 63;
            const float* ar = agg + n*HDIM;
            float acc = 0.f;
#pragma unroll 8
            for (int h = 0; h < HDIM; ++h)
                acc = fmaf(ar[h], w3[h*FDIM + j], acc);
            float kv = tanhf(acc * inv_n + sb3[j]);
            int gi = (b*NNODE + rstart + n)*FDIM + j;
            float yv = g_y[gi];
            float yin;
            if (stage == 0)      { g_ksum[gi] = kv;        yin = yv + 0.5f*dt*kv; }
            else if (stage == 1) { g_ksum[gi] += 2.f*kv;   yin = yv + 0.5f*dt*kv; }
            else if (stage == 2) { g_ksum[gi] += 2.f*kv;   yin = yv + dt*kv; }
            else {
                float yn = yv + dt*(1.f/6.f)*(g_ksum[gi] + kv);
                g_y[gi] = yn;
                out[(b*NNODE + rstart + n)*(TSTEPS*FDIM) + (t+1)*FDIM + j] = yn;
                yin = yn;
            }
            g_ybf[gi] = __float2bfloat16(yin);
        }
    }
}

// ---------------- launcher ----------------
extern "C" void kernel_launch(void* const* d_in, const int* in_sizes, int n_in,
                              void* d_out, int out_size) {
    const float* fp    = (const float*)d_in[0];
    const float* ts    = (const float*)d_in[1];
    const int*   graph = (const int*)d_in[2];
    const float* W1    = (const float*)d_in[3];
    const float* b1    = (const float*)d_in[4];
    const float* W2    = (const float*)d_in[5];
    const float* b2    = (const float*)d_in[6];
    const float* W3    = (const float*)d_in[7];
    const float* b3    = (const float*)d_in[8];
    float* out = (float*)d_out;

    cudaFuncSetAttribute(edge_kernel, cudaFuncAttributeMaxDynamicSharedMemorySize, SMEM_TOTAL);

    prep_kernel<<<256, 256>>>(fp, W1, W2, out);
    sort_kernel<<<NCTA, 32>>>(graph);
    for (int t = 0; t < TSTEPS - 1; ++t)
        for (int st = 0; st < 4; ++st)
            edge_kernel<<<NCTA, 256, SMEM_TOTAL>>>(b1, b2, W3, b3, ts, t, st, out);
}

// round 7
// speedup vs baseline: 1.3186x; 1.1844x over previous
#include <cuda_runtime.h>
#include <cuda_bf16.h>
#include <cstdint>

#define BATCH 64
#define NNODE 50
#define FDIM 64
#define HDIM 128
#define EDGES 2450
#define TSTEPS 40
#define CHUNK 128
#define MAXROWS 896
#define NQ 4
#define NCTA (BATCH*NQ)      // 256

// ---- smem byte offsets ----
#define OFF_W    0           // 4 tiles x 16KB (W1 h0,h1, W2 h0,h1 of current k)
#define OFF_PRE0 65536       // 16384
#define OFF_PRE1 81920       // 16384
#define OFF_Y    98304       // 6400
#define OFF_B1   104704
#define OFF_B2   105728
#define OFF_B3   106752
#define OFF_AGG  107008      // S tile (16x136 bf16 = 4352B) during chunks; agg fp32 after
#define OFF_RT   113664      // 512
#define SMEM_TOTAL 114176

#define SWZ(o) ((o) ^ (((o) >> 3) & 0x70))
#define SSTRIDE 136          // S tile bf16 stride (272B: conflict-free for 8xg LDS)

// ---------------- device scratch ----------------
__device__ float          g_y[BATCH*NNODE*FDIM];
__device__ float          g_ksum[BATCH*NNODE*FDIM];
__device__ __nv_bfloat16  g_ybf[BATCH*NNODE*FDIM];
__device__ __nv_bfloat16  g_Wt[8*8192];
__device__ int            g_rows[NCTA*MAXROWS];
__device__ int            g_nrows[NCTA];

// ---------------- helpers ----------------
__device__ __forceinline__ void mma16816(float* c, const uint32_t* a, const uint32_t* b) {
    asm volatile(
        "mma.sync.aligned.m16n8k16.row.col.f32.bf16.bf16.f32 "
        "{%0,%1,%2,%3}, {%4,%5,%6,%7}, {%8,%9}, {%0,%1,%2,%3};\n"
        : "+f"(c[0]), "+f"(c[1]), "+f"(c[2]), "+f"(c[3])
        : "r"(a[0]), "r"(a[1]), "r"(a[2]), "r"(a[3]), "r"(b[0]), "r"(b[1]));
}
__device__ __forceinline__ void ldsm4(uint32_t* r, uint32_t addr) {
    asm volatile("ldmatrix.sync.aligned.m8n8.x4.shared.b16 {%0,%1,%2,%3}, [%4];"
                 : "=r"(r[0]), "=r"(r[1]), "=r"(r[2]), "=r"(r[3]) : "r"(addr));
}
__device__ __forceinline__ void ldsm4t(uint32_t* r, uint32_t addr) {
    asm volatile("ldmatrix.sync.aligned.m8n8.x4.trans.shared.b16 {%0,%1,%2,%3}, [%4];"
                 : "=r"(r[0]), "=r"(r[1]), "=r"(r[2]), "=r"(r[3]) : "r"(addr));
}
__device__ __forceinline__ uint32_t smem_u32(const void* p) {
    uint32_t a;
    asm("{ .reg .u64 t; cvta.to.shared.u64 t, %1; cvt.u32.u64 %0, t; }" : "=r"(a) : "l"(p));
    return a;
}
__device__ __forceinline__ uint32_t packbf(float x, float y) {
    __nv_bfloat162 t = __floats2bfloat162_rn(x, y);
    return *reinterpret_cast<uint32_t*>(&t);
}

// ---------------- prep ----------------
__global__ void prep_kernel(const float* __restrict__ fp,
                            const float* __restrict__ W1,
                            const float* __restrict__ W2,
                            float* __restrict__ out) {
    int gsz = gridDim.x * blockDim.x;
    int g0  = blockIdx.x * blockDim.x + threadIdx.x;
    for (int i = g0; i < 4*HDIM*HDIM; i += gsz) {
        int s = i >> 14, rem = i & 16383;
        int n = rem >> 7, k = rem & 127;
        float v = (s < 2) ? W1[s*16384 + k*HDIM + n] : W2[(s-2)*16384 + k*HDIM + n];
        int tile = s*2 + (k >> 6);
        uint32_t boff = (uint32_t)(n*128 + (k & 63)*2);
        g_Wt[tile*8192 + (SWZ(boff) >> 1)] = __float2bfloat16(v);
    }
    for (int i = g0; i < BATCH*NNODE*FDIM; i += gsz) {
        float v = fp[i];
        g_y[i]   = v;
        g_ybf[i] = __float2bfloat16(v);
        out[(i >> 6)*(TSTEPS*FDIM) + (i & 63)] = v;
    }
}

// ---------------- sort: per-quarter stable partition by type ----------------
__global__ void sort_kernel(const int* __restrict__ graph) {
    const int cta = blockIdx.x;
    const int b = cta >> 2, q = cta & 3;
    const int rstart = (q < 2) ? q*13 : 26 + (q-2)*12;
    const int rcnt   = (q < 2) ? 13 : 12;
    const int ebase  = rstart * 49;
    const int ecnt   = rcnt * 49;
    const int lane = threadIdx.x;
    int* rows = g_rows + cta * MAXROWS;
    int row = 0;
#pragma unroll
    for (int k = 0; k < 2; ++k) {
        for (int i0 = 0; i0 < ecnt; i0 += 32) {
            int i = i0 + lane;
            bool m = false; int meta = 0;
            if (i < ecnt) {
                int e = ebase + i;
                int kk = graph[b*EDGES + e];
                int r = e / 49, j = e - r*49;
                int s = j + (j >= r);
                meta = (kk << 16) | (r << 8) | s;
                m = (kk == k);
            }
            unsigned mask = __ballot_sync(0xffffffffu, m);
            if (m) rows[row + __popc(mask & ((1u << lane) - 1u))] = meta;
            row += __popc(mask);
        }
        int pad = (128 - (row & 127)) & 127;
        for (int i = lane; i < pad; i += 32) rows[row + i] = -1;
        row += pad;
    }
    if (lane == 0) g_nrows[cta] = row;
}

// ---------------- fused edge+node kernel ----------------
__global__ void __launch_bounds__(256, 2)
edge_kernel(const float* __restrict__ b1f, const float* __restrict__ b2f,
            const float* __restrict__ W3,  const float* __restrict__ b3f,
            const float* __restrict__ ts,  int t, int stage,
            float* __restrict__ out) {
    extern __shared__ char smb[];
    const int tid  = threadIdx.x;
    const int lane = tid & 31, wid = tid >> 5;
    const int cta  = blockIdx.x;
    const int b = cta >> 2, q = cta & 3;
    const int rstart = (q < 2) ? q*13 : 26 + (q-2)*12;
    const int nloc   = (q < 2) ? 13 : 12;

    {
        const uint4* src = reinterpret_cast<const uint4*>(g_ybf + b*NNODE*FDIM);
        uint4* dst = reinterpret_cast<uint4*>(smb + OFF_Y);
        for (int i = tid; i < 6400/16; i += 256) dst[i] = src[i];
    }
    ((float*)(smb + OFF_B1))[tid] = b1f[tid];
    ((float*)(smb + OFF_B2))[tid] = b2f[tid];
    if (tid < 64) ((float*)(smb + OFF_B3))[tid] = b3f[tid];

    const float* sB1 = (float*)(smb + OFF_B1);
    const float* sB2 = (float*)(smb + OFF_B2);
    int* sRt = (int*)(smb + OFF_RT);
    __nv_bfloat16* sS = (__nv_bfloat16*)(smb + OFF_AGG);

    const int nch = g_nrows[cta] >> 7;
    const int* __restrict__ rows = g_rows + cta * MAXROWS;

    const int wm = (wid & 1) * 64;
    const int wn = (wid >> 1) * 32;
    const int g = lane >> 2, tig = lane & 3;
    const int li = lane & 7, lm = lane >> 3;
    const int aRow = (lm & 1)*8 + li;
    const int aK16 = (lm >> 1) * 16;
    const int bRow = (lm >> 1)*8 + li;
    const int bK16 = (lm & 1) * 16;

    const uint32_t uPre0 = smem_u32(smb + OFF_PRE0);
    const uint32_t uPre1 = smem_u32(smb + OFF_PRE1);
    const uint32_t uW    = smem_u32(smb + OFF_W);
    const uint32_t uS    = smem_u32(smb + OFF_AGG);

    // agg-GEMM invariants: warp owns cols wid*16..wid*16+15 of m
    const uint32_t aggBase = (wid >= 4) ? uPre1 : uPre0;
    const uint32_t aggColB = (uint32_t)((((wid & 3)*16) + (lm >> 1)*8) * 2);
    const uint32_t aggRowL = (uint32_t)((lm & 1)*8 + li);
    // A(S) per-thread base (kb-invariant part)
    const uint32_t sA0 = uS + (uint32_t)(g*(SSTRIDE*2) + 2*tig*2);

    float Ca[2][4];
#pragma unroll
    for (int nt = 0; nt < 2; ++nt) { Ca[nt][0]=0.f; Ca[nt][1]=0.f; Ca[nt][2]=0.f; Ca[nt][3]=0.f; }

    int curk = -1;

    for (int ch = 0; ch < nch; ++ch) {
        const int* crow = rows + ch*CHUNK;
        const int k = (crow[0] >> 16);

        if (k != curk) {
            curk = k;
            const uint4* s1 = reinterpret_cast<const uint4*>(g_Wt + (k*2)*8192);
            const uint4* s2 = reinterpret_cast<const uint4*>(g_Wt + ((2 + k)*2)*8192);
            uint4* d1 = reinterpret_cast<uint4*>(smb + OFF_W);
            uint4* d2 = reinterpret_cast<uint4*>(smb + OFF_W + 32768);
            for (int i = tid; i < 2048; i += 256) { d1[i] = s1[i]; d2[i] = s2[i]; }
        }

        // zero S tile (16 x SSTRIDE bf16)
        {
            uint32_t* s32 = (uint32_t*)sS;
            for (int i = tid; i < 16*SSTRIDE/2; i += 256) s32[i] = 0;
        }
        // gather pre halves + receiver meta
        {
            int row = tid >> 1, hlf = tid & 1;
            int v = crow[row];
            if (hlf == 0) sRt[row] = (v < 0) ? -1 : ((v >> 8) & 255);
            char* tb = smb + (hlf ? OFF_PRE1 : OFF_PRE0);
            if (v >= 0) {
                int node = hlf ? ((v >> 8) & 255) : (v & 255);
                const uint4* src = (const uint4*)(smb + OFF_Y + node*FDIM*2);
#pragma unroll
                for (int qq = 0; qq < 8; ++qq) {
                    uint32_t o = (uint32_t)(row*128 + qq*16);
                    *(uint4*)(tb + SWZ(o)) = src[qq];
                }
            } else {
                uint4 z = make_uint4(0,0,0,0);
#pragma unroll
                for (int qq = 0; qq < 8; ++qq) {
                    uint32_t o = (uint32_t)(row*128 + qq*16);
                    *(uint4*)(tb + SWZ(o)) = z;
                }
            }
        }
        __syncthreads();

        // scatter S ones (reads sRt written before the sync)
        if (tid < 128) {
            int rr = sRt[tid];
            if (rr >= 0) sS[(rr - rstart)*SSTRIDE + tid] = __float2bfloat16(1.0f);
        }

        float C[16][4];

        // ==== GEMM1 ====
#pragma unroll
        for (int i = 0; i < 16; ++i) { C[i][0]=0.f; C[i][1]=0.f; C[i][2]=0.f; C[i][3]=0.f; }
#pragma unroll
        for (int kb = 0; kb < 8; ++kb) {
            const int half = kb >> 2;
            const uint32_t kgrp = (uint32_t)((kb & 3) * 32);
            const uint32_t aBase = half ? uPre1 : uPre0;
            uint32_t a[4][4];
#pragma unroll
            for (int mt = 0; mt < 4; ++mt) {
                uint32_t o = (uint32_t)((wm + mt*16 + aRow)*128) + kgrp + aK16;
                ldsm4(a[mt], aBase + SWZ(o));
            }
            uint32_t bf[2][4];
#pragma unroll
            for (int nt2 = 0; nt2 < 2; ++nt2) {
                uint32_t o = (uint32_t)((wn + nt2*16 + bRow)*128) + kgrp + bK16;
                ldsm4(bf[nt2], uW + half*16384u + SWZ(o));
            }
#pragma unroll
            for (int mt = 0; mt < 4; ++mt)
#pragma unroll
                for (int nt = 0; nt < 4; ++nt)
                    mma16816(C[mt*4 + nt], a[mt], &bf[nt >> 1][(nt & 1)*2]);
        }
        __syncthreads();

        // epilogue1: h = relu(C + b1[k]) -> PRE halves
        {
            const int hh = wn >> 6;
            char* tb = smb + (hh ? OFF_PRE1 : OFF_PRE0);
#pragma unroll
            for (int mt = 0; mt < 4; ++mt)
#pragma unroll
                for (int nt = 0; nt < 4; ++nt) {
                    int r0 = wm + mt*16 + g, r1 = r0 + 8;
                    int c = wn + nt*8 + 2*tig;
                    float b0v = sB1[k*HDIM + c], b1v = sB1[k*HDIM + c + 1];
                    float* x = C[mt*4 + nt];
                    uint32_t cb = (uint32_t)((c & 63)*2);
                    *(uint32_t*)(tb + SWZ((uint32_t)(r0*128) + cb)) =
                        packbf(fmaxf(x[0]+b0v,0.f), fmaxf(x[1]+b1v,0.f));
                    *(uint32_t*)(tb + SWZ((uint32_t)(r1*128) + cb)) =
                        packbf(fmaxf(x[2]+b0v,0.f), fmaxf(x[3]+b1v,0.f));
                }
        }
        __syncthreads();

        // ==== GEMM2 ====
#pragma unroll
        for (int i = 0; i < 16; ++i) { C[i][0]=0.f; C[i][1]=0.f; C[i][2]=0.f; C[i][3]=0.f; }
#pragma unroll
        for (int kb = 0; kb < 8; ++kb) {
            const int half = kb >> 2;
            const uint32_t kgrp = (uint32_t)((kb & 3) * 32);
            const uint32_t aBase = half ? uPre1 : uPre0;
            uint32_t a[4][4];
#pragma unroll
            for (int mt = 0; mt < 4; ++mt) {
                uint32_t o = (uint32_t)((wm + mt*16 + aRow)*128) + kgrp + aK16;
                ldsm4(a[mt], aBase + SWZ(o));
            }
            uint32_t bf[2][4];
#pragma unroll
            for (int nt2 = 0; nt2 < 2; ++nt2) {
                uint32_t o = (uint32_t)((wn + nt2*16 + bRow)*128) + kgrp + bK16;
                ldsm4(bf[nt2], uW + 32768u + half*16384u + SWZ(o));
            }
#pragma unroll
            for (int mt = 0; mt < 4; ++mt)
#pragma unroll
                for (int nt = 0; nt < 4; ++nt)
                    mma16816(C[mt*4 + nt], a[mt], &bf[nt >> 1][(nt & 1)*2]);
        }
        __syncthreads();

        // epilogue2: m = relu(C + b2[k]) -> PRE halves
        {
            const int hh = wn >> 6;
            char* tb = smb + (hh ? OFF_PRE1 : OFF_PRE0);
#pragma unroll
            for (int mt = 0; mt < 4; ++mt)
#pragma unroll
                for (int nt = 0; nt < 4; ++nt) {
                    int r0 = wm + mt*16 + g, r1 = r0 + 8;
                    int c = wn + nt*8 + 2*tig;
                    float b0v = sB2[k*HDIM + c], b1v = sB2[k*HDIM + c + 1];
                    float* x = C[mt*4 + nt];
                    uint32_t cb = (uint32_t)((c & 63)*2);
                    *(uint32_t*)(tb + SWZ((uint32_t)(r0*128) + cb)) =
                        packbf(fmaxf(x[0]+b0v,0.f), fmaxf(x[1]+b1v,0.f));
                    *(uint32_t*)(tb + SWZ((uint32_t)(r1*128) + cb)) =
                        packbf(fmaxf(x[2]+b0v,0.f), fmaxf(x[3]+b1v,0.f));
                }
        }
        __syncthreads();

        // ==== agg GEMM: Ca += S @ m (A from S tile via LDS.32, B via ldmatrix.trans) ====
#pragma unroll
        for (int kb = 0; kb < 8; ++kb) {
            uint32_t a[4];
            uint32_t aoff = sA0 + (uint32_t)(kb*32);
            asm volatile("ld.shared.b32 %0, [%1];" : "=r"(a[0]) : "r"(aoff));
            asm volatile("ld.shared.b32 %0, [%1];" : "=r"(a[1]) : "r"(aoff + 8*(SSTRIDE*2)));
            asm volatile("ld.shared.b32 %0, [%1];" : "=r"(a[2]) : "r"(aoff + 16));
            asm volatile("ld.shared.b32 %0, [%1];" : "=r"(a[3]) : "r"(aoff + 8*(SSTRIDE*2) + 16));
            uint32_t bf[4];
            uint32_t o = (uint32_t)((kb*16 + aggRowL)*128) + aggColB;
            ldsm4t(bf, aggBase + SWZ(o));
            mma16816(Ca[0], a, bf);
            mma16816(Ca[1], a, bf + 2);
        }
        __syncthreads();
    }

    // write register agg to smem (S region reused as fp32 agg [nloc][128])
    {
        float* agg = (float*)(smb + OFF_AGG);
#pragma unroll
        for (int nt = 0; nt < 2; ++nt) {
            int c = wid*16 + nt*8 + 2*tig;
            if (g < nloc) {
                agg[g*HDIM + c]     = Ca[nt][0];
                agg[g*HDIM + c + 1] = Ca[nt][1];
            }
            if (g + 8 < nloc) {
                agg[(g+8)*HDIM + c]     = Ca[nt][2];
                agg[(g+8)*HDIM + c + 1] = Ca[nt][3];
            }
        }
    }
    __syncthreads();

    // ---- node phase ----
    {
        float* w3 = (float*)(smb + OFF_PRE0);
        for (int i = tid; i < HDIM*FDIM; i += 256) w3[i] = W3[i];
    }
    __syncthreads();
    {
        const float dt = ts[t+1] - ts[t];
        const float inv_n = 1.0f / (float)NNODE;
        const float* agg = (float*)(smb + OFF_AGG);
        const float* w3  = (float*)(smb + OFF_PRE0);
        const float* sb3 = (float*)(smb + OFF_B3);
        for (int idx = tid; idx < nloc*FDIM; idx += 256) {
            int n = idx >> 6, j = idx & 63;
            const float* ar = agg + n*HDIM;
            float acc = 0.f;
#pragma unroll 8
            for (int h = 0; h < HDIM; ++h)
                acc = fmaf(ar[h], w3[h*FDIM + j], acc);
            float kv = tanhf(acc * inv_n + sb3[j]);
            int gi = (b*NNODE + rstart + n)*FDIM + j;
            float yv = g_y[gi];
            float yin;
            if (stage == 0)      { g_ksum[gi] = kv;        yin = yv + 0.5f*dt*kv; }
            else if (stage == 1) { g_ksum[gi] += 2.f*kv;   yin = yv + 0.5f*dt*kv; }
            else if (stage == 2) { g_ksum[gi] += 2.f*kv;   yin = yv + dt*kv; }
            else {
                float yn = yv + dt*(1.f/6.f)*(g_ksum[gi] + kv);
                g_y[gi] = yn;
                out[(b*NNODE + rstart + n)*(TSTEPS*FDIM) + (t+1)*FDIM + j] = yn;
                yin = yn;
            }
            g_ybf[gi] = __float2bfloat16(yin);
        }
    }
}

// ---------------- launcher ----------------
extern "C" void kernel_launch(void* const* d_in, const int* in_sizes, int n_in,
                              void* d_out, int out_size) {
    const float* fp    = (const float*)d_in[0];
    const float* ts    = (const float*)d_in[1];
    const int*   graph = (const int*)d_in[2];
    const float* W1    = (const float*)d_in[3];
    const float* b1    = (const float*)d_in[4];
    const float* W2    = (const float*)d_in[5];
    const float* b2    = (const float*)d_in[6];
    const float* W3    = (const float*)d_in[7];
    const float* b3    = (const float*)d_in[8];
    float* out = (float*)d_out;

    cudaFuncSetAttribute(edge_kernel, cudaFuncAttributeMaxDynamicSharedMemorySize, SMEM_TOTAL);

    prep_kernel<<<256, 256>>>(fp, W1, W2, out);
    sort_kernel<<<NCTA, 32>>>(graph);
    for (int t = 0; t < TSTEPS - 1; ++t)
        for (int st = 0; st < 4; ++st)
            edge_kernel<<<NCTA, 256, SMEM_TOTAL>>>(b1, b2, W3, b3, ts, t, st, out);
}

// round 8
// speedup vs baseline: 1.3337x; 1.0114x over previous
#include <cuda_runtime.h>
#include <cuda_bf16.h>
#include <cstdint>

#define BATCH 64
#define NNODE 50
#define FDIM 64
#define HDIM 128
#define EDGES 2450
#define TSTEPS 40
#define CHUNK 128
#define MAXROWS 896
#define NQ 4
#define NCTA (BATCH*NQ)      // 256
#define NTHR 128

// ---- smem byte offsets ----
#define OFF_W    0           // 4 tiles x 16KB (W1 h0,h1, W2 h0,h1 of current k)
#define OFF_PRE0 65536       // 16384
#define OFF_PRE1 81920       // 16384
#define OFF_Y    98304       // 6400
#define OFF_B1   104704
#define OFF_B2   105728
#define OFF_B3   106752
#define OFF_AGG  107008      // S tile (16x136 bf16) during chunks; agg fp32 after
#define OFF_RT   113664      // 512
#define SMEM_TOTAL 114176

#define SWZ(o) ((o) ^ (((o) >> 3) & 0x70))
#define SSTRIDE 136

// ---------------- device scratch ----------------
__device__ float          g_y[BATCH*NNODE*FDIM];
__device__ float          g_ksum[BATCH*NNODE*FDIM];
__device__ __nv_bfloat16  g_ybf[BATCH*NNODE*FDIM];
__device__ __nv_bfloat16  g_Wt[8*8192];
__device__ int            g_rows[NCTA*MAXROWS];
__device__ int            g_nrows[NCTA];

// ---------------- helpers ----------------
__device__ __forceinline__ void mma16816(float* c, const uint32_t* a, const uint32_t* b) {
    asm volatile(
        "mma.sync.aligned.m16n8k16.row.col.f32.bf16.bf16.f32 "
        "{%0,%1,%2,%3}, {%4,%5,%6,%7}, {%8,%9}, {%0,%1,%2,%3};\n"
        : "+f"(c[0]), "+f"(c[1]), "+f"(c[2]), "+f"(c[3])
        : "r"(a[0]), "r"(a[1]), "r"(a[2]), "r"(a[3]), "r"(b[0]), "r"(b[1]));
}
__device__ __forceinline__ void ldsm4(uint32_t* r, uint32_t addr) {
    asm volatile("ldmatrix.sync.aligned.m8n8.x4.shared.b16 {%0,%1,%2,%3}, [%4];"
                 : "=r"(r[0]), "=r"(r[1]), "=r"(r[2]), "=r"(r[3]) : "r"(addr));
}
__device__ __forceinline__ void ldsm4t(uint32_t* r, uint32_t addr) {
    asm volatile("ldmatrix.sync.aligned.m8n8.x4.trans.shared.b16 {%0,%1,%2,%3}, [%4];"
                 : "=r"(r[0]), "=r"(r[1]), "=r"(r[2]), "=r"(r[3]) : "r"(addr));
}
__device__ __forceinline__ uint32_t smem_u32(const void* p) {
    uint32_t a;
    asm("{ .reg .u64 t; cvta.to.shared.u64 t, %1; cvt.u32.u64 %0, t; }" : "=r"(a) : "l"(p));
    return a;
}
__device__ __forceinline__ uint32_t packbf(float x, float y) {
    __nv_bfloat162 t = __floats2bfloat162_rn(x, y);
    return *reinterpret_cast<uint32_t*>(&t);
}

// ---------------- prep ----------------
__global__ void prep_kernel(const float* __restrict__ fp,
                            const float* __restrict__ W1,
                            const float* __restrict__ W2,
                            float* __restrict__ out) {
    int gsz = gridDim.x * blockDim.x;
    int g0  = blockIdx.x * blockDim.x + threadIdx.x;
    for (int i = g0; i < 4*HDIM*HDIM; i += gsz) {
        int s = i >> 14, rem = i & 16383;
        int n = rem >> 7, k = rem & 127;
        float v = (s < 2) ? W1[s*16384 + k*HDIM + n] : W2[(s-2)*16384 + k*HDIM + n];
        int tile = s*2 + (k >> 6);
        uint32_t boff = (uint32_t)(n*128 + (k & 63)*2);
        g_Wt[tile*8192 + (SWZ(boff) >> 1)] = __float2bfloat16(v);
    }
    for (int i = g0; i < BATCH*NNODE*FDIM; i += gsz) {
        float v = fp[i];
        g_y[i]   = v;
        g_ybf[i] = __float2bfloat16(v);
        out[(i >> 6)*(TSTEPS*FDIM) + (i & 63)] = v;
    }
}

// ---------------- sort ----------------
__global__ void sort_kernel(const int* __restrict__ graph) {
    const int cta = blockIdx.x;
    const int b = cta >> 2, q = cta & 3;
    const int rstart = (q < 2) ? q*13 : 26 + (q-2)*12;
    const int rcnt   = (q < 2) ? 13 : 12;
    const int ebase  = rstart * 49;
    const int ecnt   = rcnt * 49;
    const int lane = threadIdx.x;
    int* rows = g_rows + cta * MAXROWS;
    int row = 0;
#pragma unroll
    for (int k = 0; k < 2; ++k) {
        for (int i0 = 0; i0 < ecnt; i0 += 32) {
            int i = i0 + lane;
            bool m = false; int meta = 0;
            if (i < ecnt) {
                int e = ebase + i;
                int kk = graph[b*EDGES + e];
                int r = e / 49, j = e - r*49;
                int s = j + (j >= r);
                meta = (kk << 16) | (r << 8) | s;
                m = (kk == k);
            }
            unsigned mask = __ballot_sync(0xffffffffu, m);
            if (m) rows[row + __popc(mask & ((1u << lane) - 1u))] = meta;
            row += __popc(mask);
        }
        int pad = (128 - (row & 127)) & 127;
        for (int i = lane; i < pad; i += 32) rows[row + i] = -1;
        row += pad;
    }
    if (lane == 0) g_nrows[cta] = row;
}

// ---------------- fused edge+node kernel: 4 warps, 64x64 tiles ----------------
__global__ void __launch_bounds__(NTHR, 2)
edge_kernel(const float* __restrict__ b1f, const float* __restrict__ b2f,
            const float* __restrict__ W3,  const float* __restrict__ b3f,
            const float* __restrict__ ts,  int t, int stage,
            float* __restrict__ out) {
    extern __shared__ char smb[];
    const int tid  = threadIdx.x;
    const int lane = tid & 31, wid = tid >> 5;     // wid 0..3
    const int cta  = blockIdx.x;
    const int b = cta >> 2, q = cta & 3;
    const int rstart = (q < 2) ? q*13 : 26 + (q-2)*12;
    const int nloc   = (q < 2) ? 13 : 12;

    {
        const uint4* src = reinterpret_cast<const uint4*>(g_ybf + b*NNODE*FDIM);
        uint4* dst = reinterpret_cast<uint4*>(smb + OFF_Y);
        for (int i = tid; i < 6400/16; i += NTHR) dst[i] = src[i];
    }
    for (int i = tid; i < 2*HDIM; i += NTHR) {
        ((float*)(smb + OFF_B1))[i] = b1f[i];
        ((float*)(smb + OFF_B2))[i] = b2f[i];
    }
    if (tid < 64) ((float*)(smb + OFF_B3))[tid] = b3f[tid];

    const float* sB1 = (float*)(smb + OFF_B1);
    const float* sB2 = (float*)(smb + OFF_B2);
    int* sRt = (int*)(smb + OFF_RT);
    __nv_bfloat16* sS = (__nv_bfloat16*)(smb + OFF_AGG);

    const int nch = g_nrows[cta] >> 7;
    const int* __restrict__ rows = g_rows + cta * MAXROWS;

    // warp tiling: 2x2 grid of 64x64 tiles
    const int wm = (wid & 1) * 64;
    const int wn = (wid >> 1) * 64;
    const int g = lane >> 2, tig = lane & 3;
    const int li = lane & 7, lm = lane >> 3;
    const int aRow = (lm & 1)*8 + li;
    const int aK16 = (lm >> 1) * 16;
    const int bRow = (lm >> 1)*8 + li;
    const int bK16 = (lm & 1) * 16;

    const uint32_t uPre0 = smem_u32(smb + OFF_PRE0);
    const uint32_t uPre1 = smem_u32(smb + OFF_PRE1);
    const uint32_t uW    = smem_u32(smb + OFF_W);
    const uint32_t uS    = smem_u32(smb + OFF_AGG);

    // agg-GEMM: warp owns m cols wid*32..wid*32+31
    const uint32_t aggBase = (wid >> 1) ? uPre1 : uPre0;
    const uint32_t aggRowL = (uint32_t)((lm & 1)*8 + li);
    const uint32_t aggColL = (uint32_t)(((wid & 1)*32 + (lm >> 1)*8) * 2);
    const uint32_t sA0 = uS + (uint32_t)(g*(SSTRIDE*2) + 2*tig*2);

    float Ca[4][4];
#pragma unroll
    for (int i = 0; i < 4; ++i) { Ca[i][0]=0.f; Ca[i][1]=0.f; Ca[i][2]=0.f; Ca[i][3]=0.f; }

    int curk = -1;

    for (int ch = 0; ch < nch; ++ch) {
        const int* crow = rows + ch*CHUNK;
        const int k = (crow[0] >> 16);

        if (k != curk) {
            curk = k;
            const uint4* s1 = reinterpret_cast<const uint4*>(g_Wt + (k*2)*8192);
            const uint4* s2 = reinterpret_cast<const uint4*>(g_Wt + ((2 + k)*2)*8192);
            uint4* d1 = reinterpret_cast<uint4*>(smb + OFF_W);
            uint4* d2 = reinterpret_cast<uint4*>(smb + OFF_W + 32768);
            for (int i = tid; i < 2048; i += NTHR) { d1[i] = s1[i]; d2[i] = s2[i]; }
        }

        // zero S tile
        {
            uint32_t* s32 = (uint32_t*)sS;
            for (int i = tid; i < 16*SSTRIDE/2; i += NTHR) s32[i] = 0;
        }
        // gather: one row per thread (both halves) + receiver meta
        {
            int row = tid;
            int v = crow[row];
            sRt[row] = (v < 0) ? -1 : ((v >> 8) & 255);
            if (v >= 0) {
                int nsend = v & 255, nrecv = (v >> 8) & 255;
                const uint4* s0 = (const uint4*)(smb + OFF_Y + nsend*FDIM*2);
                const uint4* s1 = (const uint4*)(smb + OFF_Y + nrecv*FDIM*2);
#pragma unroll
                for (int qq = 0; qq < 8; ++qq) {
                    uint32_t o = SWZ((uint32_t)(row*128 + qq*16));
                    *(uint4*)(smb + OFF_PRE0 + o) = s0[qq];
                    *(uint4*)(smb + OFF_PRE1 + o) = s1[qq];
                }
            } else {
                uint4 z = make_uint4(0,0,0,0);
#pragma unroll
                for (int qq = 0; qq < 8; ++qq) {
                    uint32_t o = SWZ((uint32_t)(row*128 + qq*16));
                    *(uint4*)(smb + OFF_PRE0 + o) = z;
                    *(uint4*)(smb + OFF_PRE1 + o) = z;
                }
            }
        }
        __syncthreads();

        // scatter S ones
        if (tid < 128) {
            int rr = sRt[tid];
            if (rr >= 0) sS[(rr - rstart)*SSTRIDE + tid] = __float2bfloat16(1.0f);
        }

        float C[32][4];

        // ==== GEMM1: C[64x64] = pre @ W1[k]^T ====
#pragma unroll
        for (int i = 0; i < 32; ++i) { C[i][0]=0.f; C[i][1]=0.f; C[i][2]=0.f; C[i][3]=0.f; }
#pragma unroll
        for (int kb = 0; kb < 8; ++kb) {
            const int half = kb >> 2;
            const uint32_t kgrp = (uint32_t)((kb & 3) * 32);
            const uint32_t aBase = half ? uPre1 : uPre0;
            uint32_t a[4][4];
#pragma unroll
            for (int mt = 0; mt < 4; ++mt) {
                uint32_t o = (uint32_t)((wm + mt*16 + aRow)*128) + kgrp + aK16;
                ldsm4(a[mt], aBase + SWZ(o));
            }
            uint32_t bf[4][4];
#pragma unroll
            for (int nt2 = 0; nt2 < 4; ++nt2) {
                uint32_t o = (uint32_t)((wn + nt2*16 + bRow)*128) + kgrp + bK16;
                ldsm4(bf[nt2], uW + half*16384u + SWZ(o));
            }
#pragma unroll
            for (int mt = 0; mt < 4; ++mt)
#pragma unroll
                for (int nt = 0; nt < 8; ++nt)
                    mma16816(C[mt*8 + nt], a[mt], &bf[nt >> 1][(nt & 1)*2]);
        }
        __syncthreads();

        // epilogue1: h = relu(C + b1[k]) -> PRE halves
        {
            const int hh = wn >> 6;
            char* tb = smb + (hh ? OFF_PRE1 : OFF_PRE0);
#pragma unroll
            for (int mt = 0; mt < 4; ++mt)
#pragma unroll
                for (int nt = 0; nt < 8; ++nt) {
                    int r0 = wm + mt*16 + g, r1 = r0 + 8;
                    int c = wn + nt*8 + 2*tig;
                    float b0v = sB1[k*HDIM + c], b1v = sB1[k*HDIM + c + 1];
                    float* x = C[mt*8 + nt];
                    uint32_t cb = (uint32_t)((c & 63)*2);
                    *(uint32_t*)(tb + SWZ((uint32_t)(r0*128) + cb)) =
                        packbf(fmaxf(x[0]+b0v,0.f), fmaxf(x[1]+b1v,0.f));
                    *(uint32_t*)(tb + SWZ((uint32_t)(r1*128) + cb)) =
                        packbf(fmaxf(x[2]+b0v,0.f), fmaxf(x[3]+b1v,0.f));
                }
        }
        __syncthreads();

        // ==== GEMM2: C = h @ W2[k]^T ====
#pragma unroll
        for (int i = 0; i < 32; ++i) { C[i][0]=0.f; C[i][1]=0.f; C[i][2]=0.f; C[i][3]=0.f; }
#pragma unroll
        for (int kb = 0; kb < 8; ++kb) {
            const int half = kb >> 2;
            const uint32_t kgrp = (uint32_t)((kb & 3) * 32);
            const uint32_t aBase = half ? uPre1 : uPre0;
            uint32_t a[4][4];
#pragma unroll
            for (int mt = 0; mt < 4; ++mt) {
                uint32_t o = (uint32_t)((wm + mt*16 + aRow)*128) + kgrp + aK16;
                ldsm4(a[mt], aBase + SWZ(o));
            }
            uint32_t bf[4][4];
#pragma unroll
            for (int nt2 = 0; nt2 < 4; ++nt2) {
                uint32_t o = (uint32_t)((wn + nt2*16 + bRow)*128) + kgrp + bK16;
                ldsm4(bf[nt2], uW + 32768u + half*16384u + SWZ(o));
            }
#pragma unroll
            for (int mt = 0; mt < 4; ++mt)
#pragma unroll
                for (int nt = 0; nt < 8; ++nt)
                    mma16816(C[mt*8 + nt], a[mt], &bf[nt >> 1][(nt & 1)*2]);
        }
        __syncthreads();

        // epilogue2: m = relu(C + b2[k]) -> PRE halves
        {
            const int hh = wn >> 6;
            char* tb = smb + (hh ? OFF_PRE1 : OFF_PRE0);
#pragma unroll
            for (int mt = 0; mt < 4; ++mt)
#pragma unroll
                for (int nt = 0; nt < 8; ++nt) {
                    int r0 = wm + mt*16 + g, r1 = r0 + 8;
                    int c = wn + nt*8 + 2*tig;
                    float b0v = sB2[k*HDIM + c], b1v = sB2[k*HDIM + c + 1];
                    float* x = C[mt*8 + nt];
                    uint32_t cb = (uint32_t)((c & 63)*2);
                    *(uint32_t*)(tb + SWZ((uint32_t)(r0*128) + cb)) =
                        packbf(fmaxf(x[0]+b0v,0.f), fmaxf(x[1]+b1v,0.f));
                    *(uint32_t*)(tb + SWZ((uint32_t)(r1*128) + cb)) =
                        packbf(fmaxf(x[2]+b0v,0.f), fmaxf(x[3]+b1v,0.f));
                }
        }
        __syncthreads();

        // ==== agg GEMM: Ca += S @ m (warp owns m cols wid*32..+31) ====
#pragma unroll
        for (int kb = 0; kb < 8; ++kb) {
            uint32_t a[4];
            uint32_t aoff = sA0 + (uint32_t)(kb*32);
            asm volatile("ld.shared.b32 %0, [%1];" : "=r"(a[0]) : "r"(aoff));
            asm volatile("ld.shared.b32 %0, [%1];" : "=r"(a[1]) : "r"(aoff + 8*(SSTRIDE*2)));
            asm volatile("ld.shared.b32 %0, [%1];" : "=r"(a[2]) : "r"(aoff + 16));
            asm volatile("ld.shared.b32 %0, [%1];" : "=r"(a[3]) : "r"(aoff + 8*(SSTRIDE*2) + 16));
#pragma unroll
            for (int c2 = 0; c2 < 2; ++c2) {
                uint32_t bf[4];
                uint32_t o = (uint32_t)((kb*16 + aggRowL)*128) + aggColL + (uint32_t)(c2*32);
                ldsm4t(bf, aggBase + SWZ(o));
                mma16816(Ca[c2*2],     a, bf);
                mma16816(Ca[c2*2 + 1], a, bf + 2);
            }
        }
        __syncthreads();
    }

    // write register agg to smem (S region reused as fp32 agg [nloc][128])
    {
        float* agg = (float*)(smb + OFF_AGG);
#pragma unroll
        for (int i = 0; i < 4; ++i) {
            int c = wid*32 + i*8 + 2*tig;
            if (g < nloc) {
                agg[g*HDIM + c]     = Ca[i][0];
                agg[g*HDIM + c + 1] = Ca[i][1];
            }
            if (g + 8 < nloc) {
                agg[(g+8)*HDIM + c]     = Ca[i][2];
                agg[(g+8)*HDIM + c + 1] = Ca[i][3];
            }
        }
    }
    __syncthreads();

    // ---- node phase ----
    {
        float* w3 = (float*)(smb + OFF_PRE0);
        for (int i = tid; i < HDIM*FDIM; i += NTHR) w3[i] = W3[i];
    }
    __syncthreads();
    {
        const float dt = ts[t+1] - ts[t];
        const float inv_n = 1.0f / (float)NNODE;
        const float* agg = (float*)(smb + OFF_AGG);
        const float* w3  = (float*)(smb + OFF_PRE0);
        const float* sb3 = (float*)(smb + OFF_B3);
        for (int idx = tid; idx < nloc*FDIM; idx += NTHR) {
            int n = idx >> 6, j = idx & 63;
            const float* ar = agg + n*HDIM;
            float acc = 0.f;
#pragma unroll 8
            for (int h = 0; h < HDIM; ++h)
                acc = fmaf(ar[h], w3[h*FDIM + j], acc);
            float kv = tanhf(acc * inv_n + sb3[j]);
            int gi = (b*NNODE + rstart + n)*FDIM + j;
            float yv = g_y[gi];
            float yin;
            if (stage == 0)      { g_ksum[gi] = kv;        yin = yv + 0.5f*dt*kv; }
            else if (stage == 1) { g_ksum[gi] += 2.f*kv;   yin = yv + 0.5f*dt*kv; }
            else if (stage == 2) { g_ksum[gi] += 2.f*kv;   yin = yv + dt*kv; }
            else {
                float yn = yv + dt*(1.f/6.f)*(g_ksum[gi] + kv);
                g_y[gi] = yn;
                out[(b*NNODE + rstart + n)*(TSTEPS*FDIM) + (t+1)*FDIM + j] = yn;
                yin = yn;
            }
            g_ybf[gi] = __float2bfloat16(yin);
        }
    }
}

// ---------------- launcher ----------------
extern "C" void kernel_launch(void* const* d_in, const int* in_sizes, int n_in,
                              void* d_out, int out_size) {
    const float* fp    = (const float*)d_in[0];
    const float* ts    = (const float*)d_in[1];
    const int*   graph = (const int*)d_in[2];
    const float* W1    = (const float*)d_in[3];
    const float* b1    = (const float*)d_in[4];
    const float* W2    = (const float*)d_in[5];
    const float* b2    = (const float*)d_in[6];
    const float* W3    = (const float*)d_in[7];
    const float* b3    = (const float*)d_in[8];
    float* out = (float*)d_out;

    cudaFuncSetAttribute(edge_kernel, cudaFuncAttributeMaxDynamicSharedMemorySize, SMEM_TOTAL);

    prep_kernel<<<256, 256>>>(fp, W1, W2, out);
    sort_kernel<<<NCTA, 32>>>(graph);
    for (int t = 0; t < TSTEPS - 1; ++t)
        for (int st = 0; st < 4; ++st)
            edge_kernel<<<NCTA, NTHR, SMEM_TOTAL>>>(b1, b2, W3, b3, ts, t, st, out);
}